// round 13
// baseline (speedup 1.0000x reference)
#include <cuda_runtime.h>
#include <cuda_fp16.h>
#include <math.h>
#include <stdint.h>

#define LEN   3072
#define HID   3072
#define NH    24
#define HD    128
#define MLPD  12288
#define N1    (3*HID + MLPD)   // 21504
#define N2    (HID + MLPD)     // 15360
#define NQKV  (3*HID)          // 9216
#define EPSF  1e-6f

// ---------------- scratch ----------------------------------------------------
__device__ float g_mod[3*HID];
__device__ __align__(256) __half g_a1[(size_t)LEN*HID];
__device__ __align__(256) __half g_w1[(size_t)N1*HID];
__device__ __align__(256) __half g_a2[(size_t)LEN*N2];          // [attn | gelu(mlp)]
__device__ __align__(256) __half g_w2[(size_t)HID*N2];
__device__ __align__(256) __half g_qh[(size_t)NH*LEN*HD];
__device__ __align__(256) __half g_kh[(size_t)NH*LEN*HD];
__device__ __align__(256) __half g_vT[(size_t)NH*HD*LEN];       // [h][d][l]

__device__ __forceinline__ uint32_t smem_u32(const void* p) {
    uint32_t a;
    asm("{ .reg .u64 t; cvta.to.shared.u64 t, %1; cvt.u32.u64 %0, t; }" : "=r"(a) : "l"(p));
    return a;
}

// ------- fp16 HMMA GEMM: 128x128 tile, 4 warps (2x2) of 64x64, 2 CTA/SM -----
#define PITCH 80
#define ATILE (128*PITCH)
#define STGSZ (2*ATILE)
#define NSTG  3
#define SMEMB (NSTG*STGSZ)            // 61440

// EPI: 0 = lin2: fp32 out = xres + gate*(acc+bias)
//      3 = lin1: q/k tiles -> RMS+RoPE -> g_qh/g_kh; v tiles -> transpose -> g_vT;
//          mlp tiles -> gelu -> g_a2
template<int EPI>
__global__ void __launch_bounds__(128, 2) gemm_h(
    const __half* __restrict__ A, const __half* __restrict__ B,
    const float* __restrict__ bias, void* __restrict__ Cv,
    int ldC, int K,
    const float* __restrict__ pe, const float* __restrict__ qsc,
    const float* __restrict__ ksc, const float* __restrict__ xres)
{
    extern __shared__ char smem[];
    const uint32_t sb = smem_u32(smem);
    const int tid = threadIdx.x, lane = tid & 31, wid = tid >> 5;
    const int wm = wid & 1, wn = wid >> 1;            // 2m x 2n warps, 64x64 each
    const int m0 = blockIdx.x * 128, n0 = blockIdx.y * 128;
    const int KT = K >> 5;

    auto load_stage = [&](int buf, int kt) {
        const int k0 = kt << 5;
        #pragma unroll
        for (int i = 0; i < 8; i++) {                 // 1024 chunks / 128 thr
            int idx = tid + (i << 7);
            int isB = idx >> 9;
            int r = (idx & 511) >> 2, ch = idx & 3;
            const __half* src = (isB ? B + (size_t)(n0 + r) * K
                                     : A + (size_t)(m0 + r) * K) + k0 + ch * 8;
            uint32_t dst = sb + buf * STGSZ + isB * ATILE + r * PITCH + ch * 16;
            asm volatile("cp.async.cg.shared.global [%0], [%1], 16;"
                         :: "r"(dst), "l"(src) : "memory");
        }
    };

    float acc[4][8][4];
    #pragma unroll
    for (int a = 0; a < 4; a++)
        #pragma unroll
        for (int b = 0; b < 8; b++)
            #pragma unroll
            for (int c = 0; c < 4; c++) acc[a][b][c] = 0.f;

    const int aRow = (lane & 7) + ((lane >> 3) & 1) * 8, aK = (lane >> 4) * 16;
    const int bRow = (lane & 7) + (lane >> 4) * 8,       bK = ((lane >> 3) & 1) * 16;
    const uint32_t aAdr0 = (uint32_t)((wm * 64 + aRow) * PITCH + aK);
    const uint32_t bAdr0 = (uint32_t)(ATILE + (wn * 64 + bRow) * PITCH + bK);

    load_stage(0, 0);
    asm volatile("cp.async.commit_group;" ::: "memory");
    if (KT > 1) load_stage(1, 1);
    asm volatile("cp.async.commit_group;" ::: "memory");

    for (int kt = 0; kt < KT; kt++) {
        asm volatile("cp.async.wait_group 1;" ::: "memory");
        __syncthreads();
        int nk = kt + 2;
        if (nk < KT) load_stage(nk % NSTG, nk);
        asm volatile("cp.async.commit_group;" ::: "memory");

        const uint32_t base = sb + (kt % NSTG) * STGSZ;
        #pragma unroll
        for (int ks = 0; ks < 2; ks++) {
            uint32_t ra[4][4], rb[4][4];
            #pragma unroll
            for (int mt = 0; mt < 4; mt++) {
                uint32_t ad = base + aAdr0 + mt * (16 * PITCH) + ks * 32;
                asm volatile("ldmatrix.sync.aligned.m8n8.x4.shared.b16 {%0,%1,%2,%3}, [%4];"
                    : "=r"(ra[mt][0]), "=r"(ra[mt][1]), "=r"(ra[mt][2]), "=r"(ra[mt][3])
                    : "r"(ad));
            }
            #pragma unroll
            for (int nt = 0; nt < 4; nt++) {
                uint32_t bd = base + bAdr0 + nt * (16 * PITCH) + ks * 32;
                asm volatile("ldmatrix.sync.aligned.m8n8.x4.shared.b16 {%0,%1,%2,%3}, [%4];"
                    : "=r"(rb[nt][0]), "=r"(rb[nt][1]), "=r"(rb[nt][2]), "=r"(rb[nt][3])
                    : "r"(bd));
            }
            #pragma unroll
            for (int mt = 0; mt < 4; mt++)
                #pragma unroll
                for (int nt = 0; nt < 4; nt++) {
                    #pragma unroll
                    for (int h = 0; h < 2; h++) {
                        float* c = acc[mt][nt * 2 + h];
                        asm volatile(
                            "mma.sync.aligned.m16n8k16.row.col.f32.f16.f16.f32 "
                            "{%0,%1,%2,%3}, {%4,%5,%6,%7}, {%8,%9}, {%0,%1,%2,%3};"
                            : "+f"(c[0]), "+f"(c[1]), "+f"(c[2]), "+f"(c[3])
                            : "r"(ra[mt][0]), "r"(ra[mt][1]), "r"(ra[mt][2]), "r"(ra[mt][3]),
                              "r"(rb[nt][h * 2]), "r"(rb[nt][h * 2 + 1]));
                    }
                }
        }
        __syncthreads();
    }

    const int g = lane >> 2, tig = lane & 3;

    if (EPI == 3 && n0 < NQKV) {
        asm volatile("cp.async.wait_group 0;" ::: "memory");
        __syncthreads();
        if (n0 < 2 * HID) {
            // ---- q or k tile: bias + RMS + RoPE + fp16 store ----
            const bool isq = (n0 < HID);
            const int h = (n0 - (isq ? 0 : HID)) >> 7;
            const float* sc = isq ? qsc : ksc;
            __half* dbuf = isq ? g_qh : g_kh;
            float* rsum = (float*)smem;                      // [128][2]
            float ss[4][2];
            #pragma unroll
            for (int mt = 0; mt < 4; mt++) { ss[mt][0] = 0.f; ss[mt][1] = 0.f; }
            #pragma unroll
            for (int mt = 0; mt < 4; mt++)
                #pragma unroll
                for (int j = 0; j < 8; j++) {
                    int col = wn * 64 + j * 8 + tig * 2;
                    float b0 = bias[n0 + col], b1 = bias[n0 + col + 1];
                    float t00 = acc[mt][j][0] + b0, t01 = acc[mt][j][1] + b1;
                    float t10 = acc[mt][j][2] + b0, t11 = acc[mt][j][3] + b1;
                    ss[mt][0] += t00 * t00 + t01 * t01;
                    ss[mt][1] += t10 * t10 + t11 * t11;
                }
            #pragma unroll
            for (int mt = 0; mt < 4; mt++)
                #pragma unroll
                for (int hh = 0; hh < 2; hh++) {
                    float v = ss[mt][hh];
                    v += __shfl_xor_sync(0xffffffffu, v, 1);
                    v += __shfl_xor_sync(0xffffffffu, v, 2);
                    if (tig == 0) rsum[(wm * 64 + mt * 16 + g + hh * 8) * 2 + wn] = v;
                }
            __syncthreads();
            float rr[4][2];
            #pragma unroll
            for (int mt = 0; mt < 4; mt++)
                #pragma unroll
                for (int hh = 0; hh < 2; hh++) {
                    int lr = wm * 64 + mt * 16 + g + hh * 8;
                    rr[mt][hh] = rsqrtf((rsum[lr * 2] + rsum[lr * 2 + 1]) * (1.f / HD) + EPSF);
                }
            #pragma unroll
            for (int mt = 0; mt < 4; mt++)
                #pragma unroll
                for (int j = 0; j < 8; j++) {
                    int d = wn * 64 + j * 8 + tig * 2;
                    float b0 = bias[n0 + d], b1 = bias[n0 + d + 1];
                    float s0 = sc[d], s1 = sc[d + 1];
                    #pragma unroll
                    for (int hh = 0; hh < 2; hh++) {
                        int lr = wm * 64 + mt * 16 + g + hh * 8;
                        int l = m0 + lr;
                        float t0 = (acc[mt][j][hh * 2]     + b0) * rr[mt][hh] * s0;
                        float t1 = (acc[mt][j][hh * 2 + 1] + b1) * rr[mt][hh] * s1;
                        float4 p = *(const float4*)(pe + (size_t)l * 256 + d * 2);
                        float o0 = p.x * t0 + p.y * t1;
                        float o1 = p.z * t0 + p.w * t1;
                        *(__half2*)(dbuf + ((size_t)h * LEN + l) * HD + d) =
                            __floats2half2_rn(o0, o1);
                    }
                }
        } else {
            // ---- v tile: bias + fp16, smem transpose -> g_vT ----
            const int h = (n0 - 2 * HID) >> 7;
            __half* vs = (__half*)smem;                      // [128][136]
            #pragma unroll
            for (int mt = 0; mt < 4; mt++)
                #pragma unroll
                for (int j = 0; j < 8; j++) {
                    int d = wn * 64 + j * 8 + tig * 2;
                    float b0 = bias[n0 + d], b1 = bias[n0 + d + 1];
                    #pragma unroll
                    for (int hh = 0; hh < 2; hh++) {
                        int lr = wm * 64 + mt * 16 + g + hh * 8;
                        *(__half2*)(vs + lr * 136 + d) =
                            __floats2half2_rn(acc[mt][j][hh * 2] + b0,
                                              acc[mt][j][hh * 2 + 1] + b1);
                    }
                }
            __syncthreads();
            int d = tid;                                     // 0..127
            __align__(16) __half tmp[128];
            #pragma unroll
            for (int i = 0; i < 128; i++) tmp[i] = vs[i * 136 + d];
            __half* dst = g_vT + ((size_t)h * HD + d) * LEN + m0;
            #pragma unroll
            for (int i = 0; i < 16; i++)
                *(uint4*)(dst + i * 8) = *(uint4*)(tmp + i * 8);
        }
        return;
    }

    #pragma unroll
    for (int mt = 0; mt < 4; mt++) {
        #pragma unroll
        for (int j = 0; j < 8; j++) {
            int row = m0 + wm * 64 + mt * 16 + g;
            int col = n0 + wn * 64 + j * 8 + tig * 2;
            float v00 = acc[mt][j][0], v01 = acc[mt][j][1];
            float v10 = acc[mt][j][2], v11 = acc[mt][j][3];
            if (EPI == 0) {
                float b0 = bias[col], b1 = bias[col + 1];
                float g0 = g_mod[2 * HID + col], g1 = g_mod[2 * HID + col + 1];
                float* C = (float*)Cv;
                float2 x0 = *(const float2*)(xres + (size_t)row * HID + col);
                float2 x1 = *(const float2*)(xres + (size_t)(row + 8) * HID + col);
                float2 a0 = { x0.x + g0 * (v00 + b0), x0.y + g1 * (v01 + b1) };
                float2 a1 = { x1.x + g0 * (v10 + b0), x1.y + g1 * (v11 + b1) };
                *(float2*)(C + (size_t)row * ldC + col) = a0;
                *(float2*)(C + (size_t)(row + 8) * ldC + col) = a1;
            } else {  // EPI == 3, mlp tile
                float b0 = bias[col], b1 = bias[col + 1];
                v00 += b0; v01 += b1; v10 += b0; v11 += b1;
                auto gelu = [](float v) {
                    float inr = 0.7978845608028654f * (v + 0.044715f * v * v * v);
                    return 0.5f * v * (1.f + tanhf(inr));
                };
                int c2 = HID + (col - NQKV);
                *(__half2*)(g_a2 + (size_t)row * N2 + c2) = __floats2half2_rn(gelu(v00), gelu(v01));
                *(__half2*)(g_a2 + (size_t)(row + 8) * N2 + c2) = __floats2half2_rn(gelu(v10), gelu(v11));
            }
        }
    }
}

// ---------------- flash attention (unchanged from R11) -----------------------
#define FA_Q    0
#define FA_KV   40960
#define FA_KVSZ 81920
#define FA_SMEM 204800
#define NKT     (LEN/128)      // 24

__global__ void __launch_bounds__(256, 1) flash_attn() {
    extern __shared__ char smem[];
    const uint32_t sb = smem_u32(smem);
    const int tid = threadIdx.x, lane = tid & 31, wid = tid >> 5;
    const int g = lane >> 2, tig = lane & 3;
    const int m0 = blockIdx.x * 128;
    const int h = blockIdx.y;
    const float alpha = 0.08838834764831845f;

    #pragma unroll
    for (int i = 0; i < 8; i++) {
        int q = tid + (i << 8);
        int r = q >> 4, c = q & 15;
        const __half* src = g_qh + ((size_t)h * LEN + m0 + r) * HD + c * 8;
        uint32_t dst = sb + FA_Q + (c >> 2) * 10240 + r * 80 + (c & 3) * 16;
        asm volatile("cp.async.cg.shared.global [%0], [%1], 16;" :: "r"(dst), "l"(src) : "memory");
    }
    auto load_kv = [&](int j, int buf) {
        #pragma unroll
        for (int i = 0; i < 16; i++) {
            int idx = tid + (i << 8);
            int isV = idx >> 11;
            int e = idx & 2047;
            int r = e >> 4, c = e & 15;
            const __half* src = isV
                ? g_vT + ((size_t)h * HD + r) * LEN + j * 128 + c * 8
                : g_kh + ((size_t)h * LEN + j * 128 + r) * HD + c * 8;
            uint32_t dst = sb + FA_KV + buf * FA_KVSZ + isV * 40960
                         + (c >> 2) * 10240 + r * 80 + (c & 3) * 16;
            asm volatile("cp.async.cg.shared.global [%0], [%1], 16;" :: "r"(dst), "l"(src) : "memory");
        }
    };
    load_kv(0, 0);
    asm volatile("cp.async.commit_group;" ::: "memory");

    float o[16][4];
    #pragma unroll
    for (int a = 0; a < 16; a++)
        #pragma unroll
        for (int b = 0; b < 4; b++) o[a][b] = 0.f;
    float mrow[2] = { -1e30f, -1e30f };
    float lrow[2] = { 0.f, 0.f };

    const int aRow = (lane & 7) + ((lane >> 3) & 1) * 8, aK = (lane >> 4) * 16;
    const int bRow = (lane & 7) + (lane >> 4) * 8,       bK = ((lane >> 3) & 1) * 16;
    const uint32_t qAdr = (uint32_t)((wid * 16 + aRow) * 80 + aK);

    for (int j = 0; j < NKT; j++) {
        __syncthreads();
        if (j + 1 < NKT) load_kv(j + 1, (j + 1) & 1);
        asm volatile("cp.async.commit_group;" ::: "memory");
        asm volatile("cp.async.wait_group 1;" ::: "memory");
        __syncthreads();

        const uint32_t kb = sb + FA_KV + (j & 1) * FA_KVSZ;
        const uint32_t vb = kb + 40960;

        float s[16][4];
        #pragma unroll
        for (int a = 0; a < 16; a++)
            #pragma unroll
            for (int b = 0; b < 4; b++) s[a][b] = 0.f;
        #pragma unroll
        for (int kc = 0; kc < 4; kc++) {
            #pragma unroll
            for (int ks = 0; ks < 2; ks++) {
                uint32_t ra[4], rb[8][4];
                uint32_t ad = sb + FA_Q + kc * 10240 + qAdr + ks * 32;
                asm volatile("ldmatrix.sync.aligned.m8n8.x4.shared.b16 {%0,%1,%2,%3}, [%4];"
                    : "=r"(ra[0]), "=r"(ra[1]), "=r"(ra[2]), "=r"(ra[3]) : "r"(ad));
                #pragma unroll
                for (int bp = 0; bp < 8; bp++) {
                    uint32_t bd = kb + kc * 10240 + (bp * 16 + bRow) * 80 + ks * 32 + bK;
                    asm volatile("ldmatrix.sync.aligned.m8n8.x4.shared.b16 {%0,%1,%2,%3}, [%4];"
                        : "=r"(rb[bp][0]), "=r"(rb[bp][1]), "=r"(rb[bp][2]), "=r"(rb[bp][3])
                        : "r"(bd));
                }
                #pragma unroll
                for (int bp = 0; bp < 8; bp++)
                    #pragma unroll
                    for (int hh = 0; hh < 2; hh++) {
                        float* c = s[bp * 2 + hh];
                        asm volatile(
                            "mma.sync.aligned.m16n8k16.row.col.f32.f16.f16.f32 "
                            "{%0,%1,%2,%3}, {%4,%5,%6,%7}, {%8,%9}, {%0,%1,%2,%3};"
                            : "+f"(c[0]), "+f"(c[1]), "+f"(c[2]), "+f"(c[3])
                            : "r"(ra[0]), "r"(ra[1]), "r"(ra[2]), "r"(ra[3]),
                              "r"(rb[bp][hh * 2]), "r"(rb[bp][hh * 2 + 1]));
                    }
            }
        }

        float mj[2] = { -1e30f, -1e30f };
        #pragma unroll
        for (int nt = 0; nt < 16; nt++) {
            mj[0] = fmaxf(mj[0], fmaxf(s[nt][0], s[nt][1]));
            mj[1] = fmaxf(mj[1], fmaxf(s[nt][2], s[nt][3]));
        }
        #pragma unroll
        for (int hh = 0; hh < 2; hh++) {
            mj[hh] = fmaxf(mj[hh], __shfl_xor_sync(0xffffffffu, mj[hh], 1));
            mj[hh] = fmaxf(mj[hh], __shfl_xor_sync(0xffffffffu, mj[hh], 2));
        }
        float mnew[2] = { fmaxf(mrow[0], mj[0]), fmaxf(mrow[1], mj[1]) };
        float corr[2] = { __expf(alpha * (mrow[0] - mnew[0])),
                          __expf(alpha * (mrow[1] - mnew[1])) };
        mrow[0] = mnew[0]; mrow[1] = mnew[1];

        float rs[2] = { 0.f, 0.f };
        uint32_t phA[16], phB[16];
        #pragma unroll
        for (int nt = 0; nt < 16; nt++) {
            float e0 = __expf(alpha * (s[nt][0] - mnew[0]));
            float e1 = __expf(alpha * (s[nt][1] - mnew[0]));
            float e2 = __expf(alpha * (s[nt][2] - mnew[1]));
            float e3 = __expf(alpha * (s[nt][3] - mnew[1]));
            rs[0] += e0 + e1; rs[1] += e2 + e3;
            __half2 p0 = __floats2half2_rn(e0, e1);
            __half2 p1 = __floats2half2_rn(e2, e3);
            phA[nt] = *(uint32_t*)&p0;
            phB[nt] = *(uint32_t*)&p1;
        }
        #pragma unroll
        for (int hh = 0; hh < 2; hh++) {
            rs[hh] += __shfl_xor_sync(0xffffffffu, rs[hh], 1);
            rs[hh] += __shfl_xor_sync(0xffffffffu, rs[hh], 2);
            lrow[hh] = lrow[hh] * corr[hh] + rs[hh];
        }
        #pragma unroll
        for (int nt = 0; nt < 16; nt++) {
            o[nt][0] *= corr[0]; o[nt][1] *= corr[0];
            o[nt][2] *= corr[1]; o[nt][3] *= corr[1];
        }

        #pragma unroll
        for (int kc = 0; kc < 8; kc++) {
            uint32_t ra[4] = { phA[kc * 2], phB[kc * 2], phA[kc * 2 + 1], phB[kc * 2 + 1] };
            uint32_t rb[8][4];
            #pragma unroll
            for (int bp = 0; bp < 8; bp++) {
                uint32_t bd = vb + (kc >> 1) * 10240 + (bp * 16 + bRow) * 80 + (kc & 1) * 32 + bK;
                asm volatile("ldmatrix.sync.aligned.m8n8.x4.shared.b16 {%0,%1,%2,%3}, [%4];"
                    : "=r"(rb[bp][0]), "=r"(rb[bp][1]), "=r"(rb[bp][2]), "=r"(rb[bp][3])
                    : "r"(bd));
            }
            #pragma unroll
            for (int bp = 0; bp < 8; bp++)
                #pragma unroll
                for (int hh = 0; hh < 2; hh++) {
                    float* c = o[bp * 2 + hh];
                    asm volatile(
                        "mma.sync.aligned.m16n8k16.row.col.f32.f16.f16.f32 "
                        "{%0,%1,%2,%3}, {%4,%5,%6,%7}, {%8,%9}, {%0,%1,%2,%3};"
                        : "+f"(c[0]), "+f"(c[1]), "+f"(c[2]), "+f"(c[3])
                        : "r"(ra[0]), "r"(ra[1]), "r"(ra[2]), "r"(ra[3]),
                          "r"(rb[bp][hh * 2]), "r"(rb[bp][hh * 2 + 1]));
                }
        }
    }

    float inv0 = 1.f / lrow[0], inv1 = 1.f / lrow[1];
    int row0 = m0 + wid * 16 + g;
    #pragma unroll
    for (int nt = 0; nt < 16; nt++) {
        int col = h * 128 + nt * 8 + tig * 2;
        *(__half2*)(g_a2 + (size_t)row0 * N2 + col) =
            __floats2half2_rn(o[nt][0] * inv0, o[nt][1] * inv0);
        *(__half2*)(g_a2 + (size_t)(row0 + 8) * N2 + col) =
            __floats2half2_rn(o[nt][2] * inv1, o[nt][3] * inv1);
    }
}

// ---------------- elementwise ------------------------------------------------
__global__ void gemv_mod_kernel(const float* __restrict__ vec,
                                const float* __restrict__ W, const float* __restrict__ b) {
    int j = blockIdx.x * 8 + (threadIdx.x >> 5);
    int lane = threadIdx.x & 31;
    const float4* w4 = (const float4*)(W + (size_t)j * HID);
    const float4* v4 = (const float4*)vec;
    float acc = 0.f;
    for (int i = lane; i < HID/4; i += 32) {
        float4 w = w4[i], v = v4[i];
        acc += w.x * (v.x / (1.f + __expf(-v.x)));
        acc += w.y * (v.y / (1.f + __expf(-v.y)));
        acc += w.z * (v.z / (1.f + __expf(-v.z)));
        acc += w.w * (v.w / (1.f + __expf(-v.w)));
    }
    #pragma unroll
    for (int o = 16; o; o >>= 1) acc += __shfl_xor_sync(0xffffffffu, acc, o);
    if (lane == 0) g_mod[j] = acc + b[j];
}

__global__ void layernorm_kernel(const float* __restrict__ x) {
    __shared__ float shA[8], shB[8];
    __shared__ float s_mu, s_r;
    int l = blockIdx.x, t = threadIdx.x;
    const float* row = x + (size_t)l * HID;
    float v[12];
    float s = 0.f, ss = 0.f;
    #pragma unroll
    for (int i = 0; i < 12; i++) { v[i] = row[t + i*256]; s += v[i]; ss += v[i]*v[i]; }
    #pragma unroll
    for (int o = 16; o; o >>= 1) {
        s  += __shfl_xor_sync(0xffffffffu, s, o);
        ss += __shfl_xor_sync(0xffffffffu, ss, o);
    }
    if ((t & 31) == 0) { shA[t>>5] = s; shB[t>>5] = ss; }
    __syncthreads();
    if (t == 0) {
        float a = 0.f, bb = 0.f;
        #pragma unroll
        for (int w = 0; w < 8; w++) { a += shA[w]; bb += shB[w]; }
        float mu = a / HID;
        s_mu = mu; s_r = rsqrtf(bb / HID - mu*mu + EPSF);
    }
    __syncthreads();
    float mu = s_mu, r = s_r;
    __half* orow = g_a1 + (size_t)l * HID;
    #pragma unroll
    for (int i = 0; i < 12; i++) {
        int kc = t + i*256;
        float xm = (v[i] - mu) * r * (1.f + g_mod[HID + kc]) + g_mod[kc];
        orow[kc] = __float2half_rn(xm);
    }
}

// fp32 -> fp16, 4-way ILP grid-stride (guarded)
__global__ void conv_w(const float4* __restrict__ src, uint2* __restrict__ dst, size_t n4) {
    size_t i0 = ((size_t)blockIdx.x * blockDim.x + threadIdx.x) * 4;
    size_t stride = (size_t)gridDim.x * blockDim.x * 4;
    for (size_t i = i0; i + 3 < n4; i += stride) {
        float4 v0 = src[i], v1 = src[i+1], v2 = src[i+2], v3 = src[i+3];
        __half2 a0 = __floats2half2_rn(v0.x, v0.y), a1 = __floats2half2_rn(v0.z, v0.w);
        __half2 b0 = __floats2half2_rn(v1.x, v1.y), b1 = __floats2half2_rn(v1.z, v1.w);
        __half2 c0 = __floats2half2_rn(v2.x, v2.y), c1 = __floats2half2_rn(v2.z, v2.w);
        __half2 d0 = __floats2half2_rn(v3.x, v3.y), d1 = __floats2half2_rn(v3.z, v3.w);
        uint2 u0 = { *(uint32_t*)&a0, *(uint32_t*)&a1 };
        uint2 u1 = { *(uint32_t*)&b0, *(uint32_t*)&b1 };
        uint2 u2 = { *(uint32_t*)&c0, *(uint32_t*)&c1 };
        uint2 u3 = { *(uint32_t*)&d0, *(uint32_t*)&d1 };
        dst[i] = u0; dst[i+1] = u1; dst[i+2] = u2; dst[i+3] = u3;
    }
}

// ---------------- launcher ---------------------------------------------------
extern "C" void kernel_launch(void* const* d_in, const int* in_sizes, int n_in,
                              void* d_out, int out_size) {
    const float* x       = (const float*)d_in[0];
    const float* vec     = (const float*)d_in[1];
    const float* pe      = (const float*)d_in[2];
    const float* mod_w   = (const float*)d_in[3];
    const float* mod_b   = (const float*)d_in[4];
    const float* lin1_w  = (const float*)d_in[5];
    const float* lin1_b  = (const float*)d_in[6];
    const float* lin2_w  = (const float*)d_in[7];
    const float* lin2_b  = (const float*)d_in[8];
    const float* q_scale = (const float*)d_in[9];
    const float* k_scale = (const float*)d_in[10];
    float* out = (float*)d_out;

    void *pa1, *pw1, *pa2, *pw2;
    cudaGetSymbolAddress(&pa1, g_a1);   cudaGetSymbolAddress(&pw1, g_w1);
    cudaGetSymbolAddress(&pa2, g_a2);   cudaGetSymbolAddress(&pw2, g_w2);

    cudaFuncSetAttribute(gemm_h<0>, cudaFuncAttributeMaxDynamicSharedMemorySize, SMEMB);
    cudaFuncSetAttribute(gemm_h<3>, cudaFuncAttributeMaxDynamicSharedMemorySize, SMEMB);
    cudaFuncSetAttribute(flash_attn, cudaFuncAttributeMaxDynamicSharedMemorySize, FA_SMEM);

    gemv_mod_kernel<<<(3*HID)/8, 256>>>(vec, mod_w, mod_b);                 // 1
    layernorm_kernel<<<LEN, 256>>>(x);                                      // 2
    conv_w<<<1024, 256>>>((const float4*)lin1_w, (uint2*)pw1, (size_t)N1*HID/4); // 3

    // 4 (profiled): lin1 M=3072 N=21504 K=3072; epilogue does RMS/RoPE/vT/gelu
    gemm_h<3><<<dim3(LEN/128, N1/128, 1), 128, SMEMB>>>(
        (const __half*)pa1, (const __half*)pw1, lin1_b, nullptr,
        0, HID, pe, q_scale, k_scale, nullptr);

    conv_w<<<1024, 256>>>((const float4*)lin2_w, (uint2*)pw2, (size_t)HID*N2/4); // 5

    // 6: fused attention -> g_a2[:, h*128+d]
    flash_attn<<<dim3(LEN/128, NH), 256, FA_SMEM>>>();

    // 7: lin2 M=3072 N=3072 K=15360 -> out = x + gate*(acc+bias)
    gemm_h<0><<<dim3(LEN/128, HID/128, 1), 128, SMEMB>>>(
        (const __half*)pa2, (const __half*)pw2, lin2_b, out,
        HID, N2, nullptr, nullptr, nullptr, x);
}

// round 14
// speedup vs baseline: 1.0130x; 1.0130x over previous
#include <cuda_runtime.h>
#include <cuda_fp16.h>
#include <math.h>
#include <stdint.h>

#define LEN   3072
#define HID   3072
#define NH    24
#define HD    128
#define MLPD  12288
#define N1    (3*HID + MLPD)   // 21504
#define N2    (HID + MLPD)     // 15360
#define NQKV  (3*HID)          // 9216
#define EPSF  1e-6f

// ---------------- scratch ----------------------------------------------------
__device__ float g_mod[3*HID];
__device__ __align__(256) __half g_a1[(size_t)LEN*HID];
__device__ __align__(256) __half g_w1[(size_t)N1*HID];
__device__ __align__(256) __half g_a2[(size_t)LEN*N2];          // [attn | gelu(mlp)]
__device__ __align__(256) __half g_w2[(size_t)HID*N2];
__device__ __align__(256) __half g_qh[(size_t)NH*LEN*HD];
__device__ __align__(256) __half g_kh[(size_t)NH*LEN*HD];
__device__ __align__(256) __half g_vT[(size_t)NH*HD*LEN];       // [h][d][l]

__device__ __forceinline__ uint32_t smem_u32(const void* p) {
    uint32_t a;
    asm("{ .reg .u64 t; cvta.to.shared.u64 t, %1; cvt.u32.u64 %0, t; }" : "=r"(a) : "l"(p));
    return a;
}

// ------- fp16 HMMA GEMM: 128x128 tile, 4 warps (2x2) of 64x64, 2 CTA/SM -----
#define PITCH 80
#define ATILE (128*PITCH)
#define STGSZ (2*ATILE)
#define NSTG  3
#define SMEMB (NSTG*STGSZ)            // 61440

// EPI: 0 = lin2: fp32 out = xres + gate*(acc+bias)
//      3 = lin1: q/k tiles -> RMS+RoPE -> g_qh/g_kh; v tiles -> transpose -> g_vT;
//          mlp tiles -> gelu -> g_a2
template<int EPI>
__global__ void __launch_bounds__(128, 2) gemm_h(
    const __half* __restrict__ A, const __half* __restrict__ B,
    const float* __restrict__ bias, void* __restrict__ Cv,
    int ldC, int K,
    const float* __restrict__ pe, const float* __restrict__ qsc,
    const float* __restrict__ ksc, const float* __restrict__ xres)
{
    extern __shared__ char smem[];
    const uint32_t sb = smem_u32(smem);
    const int tid = threadIdx.x, lane = tid & 31, wid = tid >> 5;
    const int wm = wid & 1, wn = wid >> 1;            // 2m x 2n warps, 64x64 each
    const int m0 = blockIdx.x * 128, n0 = blockIdx.y * 128;
    const int KT = K >> 5;

    auto load_stage = [&](int buf, int kt) {
        const int k0 = kt << 5;
        #pragma unroll
        for (int i = 0; i < 8; i++) {                 // 1024 chunks / 128 thr
            int idx = tid + (i << 7);
            int isB = idx >> 9;
            int r = (idx & 511) >> 2, ch = idx & 3;
            const __half* src = (isB ? B + (size_t)(n0 + r) * K
                                     : A + (size_t)(m0 + r) * K) + k0 + ch * 8;
            uint32_t dst = sb + buf * STGSZ + isB * ATILE + r * PITCH + ch * 16;
            asm volatile("cp.async.cg.shared.global [%0], [%1], 16;"
                         :: "r"(dst), "l"(src) : "memory");
        }
    };

    float acc[4][8][4];
    #pragma unroll
    for (int a = 0; a < 4; a++)
        #pragma unroll
        for (int b = 0; b < 8; b++)
            #pragma unroll
            for (int c = 0; c < 4; c++) acc[a][b][c] = 0.f;

    const int aRow = (lane & 7) + ((lane >> 3) & 1) * 8, aK = (lane >> 4) * 16;
    const int bRow = (lane & 7) + (lane >> 4) * 8,       bK = ((lane >> 3) & 1) * 16;
    const uint32_t aAdr0 = (uint32_t)((wm * 64 + aRow) * PITCH + aK);
    const uint32_t bAdr0 = (uint32_t)(ATILE + (wn * 64 + bRow) * PITCH + bK);

    load_stage(0, 0);
    asm volatile("cp.async.commit_group;" ::: "memory");
    if (KT > 1) load_stage(1, 1);
    asm volatile("cp.async.commit_group;" ::: "memory");

    for (int kt = 0; kt < KT; kt++) {
        asm volatile("cp.async.wait_group 1;" ::: "memory");
        __syncthreads();
        int nk = kt + 2;
        if (nk < KT) load_stage(nk % NSTG, nk);
        asm volatile("cp.async.commit_group;" ::: "memory");

        const uint32_t base = sb + (kt % NSTG) * STGSZ;
        #pragma unroll
        for (int ks = 0; ks < 2; ks++) {
            uint32_t ra[4][4], rb[4][4];
            #pragma unroll
            for (int mt = 0; mt < 4; mt++) {
                uint32_t ad = base + aAdr0 + mt * (16 * PITCH) + ks * 32;
                asm volatile("ldmatrix.sync.aligned.m8n8.x4.shared.b16 {%0,%1,%2,%3}, [%4];"
                    : "=r"(ra[mt][0]), "=r"(ra[mt][1]), "=r"(ra[mt][2]), "=r"(ra[mt][3])
                    : "r"(ad));
            }
            #pragma unroll
            for (int nt = 0; nt < 4; nt++) {
                uint32_t bd = base + bAdr0 + nt * (16 * PITCH) + ks * 32;
                asm volatile("ldmatrix.sync.aligned.m8n8.x4.shared.b16 {%0,%1,%2,%3}, [%4];"
                    : "=r"(rb[nt][0]), "=r"(rb[nt][1]), "=r"(rb[nt][2]), "=r"(rb[nt][3])
                    : "r"(bd));
            }
            #pragma unroll
            for (int mt = 0; mt < 4; mt++)
                #pragma unroll
                for (int nt = 0; nt < 4; nt++) {
                    #pragma unroll
                    for (int h = 0; h < 2; h++) {
                        float* c = acc[mt][nt * 2 + h];
                        asm volatile(
                            "mma.sync.aligned.m16n8k16.row.col.f32.f16.f16.f32 "
                            "{%0,%1,%2,%3}, {%4,%5,%6,%7}, {%8,%9}, {%0,%1,%2,%3};"
                            : "+f"(c[0]), "+f"(c[1]), "+f"(c[2]), "+f"(c[3])
                            : "r"(ra[mt][0]), "r"(ra[mt][1]), "r"(ra[mt][2]), "r"(ra[mt][3]),
                              "r"(rb[nt][h * 2]), "r"(rb[nt][h * 2 + 1]));
                    }
                }
        }
        // NOTE: no trailing __syncthreads — the top-of-loop sync of the next
        // iteration orders this iteration's LDSM reads before any overwrite
        // of buffer (kt+3)%3 (issued only after that sync).
    }

    __syncthreads();   // ensure all warps finished mainloop before smem reuse

    const int g = lane >> 2, tig = lane & 3;

    if (EPI == 3 && n0 < NQKV) {
        asm volatile("cp.async.wait_group 0;" ::: "memory");
        __syncthreads();
        if (n0 < 2 * HID) {
            // ---- q or k tile: bias + RMS + RoPE + fp16 store ----
            const bool isq = (n0 < HID);
            const int h = (n0 - (isq ? 0 : HID)) >> 7;
            const float* sc = isq ? qsc : ksc;
            __half* dbuf = isq ? g_qh : g_kh;
            float* rsum = (float*)smem;                      // [128][2]
            float ss[4][2];
            #pragma unroll
            for (int mt = 0; mt < 4; mt++) { ss[mt][0] = 0.f; ss[mt][1] = 0.f; }
            #pragma unroll
            for (int mt = 0; mt < 4; mt++)
                #pragma unroll
                for (int j = 0; j < 8; j++) {
                    int col = wn * 64 + j * 8 + tig * 2;
                    float b0 = bias[n0 + col], b1 = bias[n0 + col + 1];
                    float t00 = acc[mt][j][0] + b0, t01 = acc[mt][j][1] + b1;
                    float t10 = acc[mt][j][2] + b0, t11 = acc[mt][j][3] + b1;
                    ss[mt][0] += t00 * t00 + t01 * t01;
                    ss[mt][1] += t10 * t10 + t11 * t11;
                }
            #pragma unroll
            for (int mt = 0; mt < 4; mt++)
                #pragma unroll
                for (int hh = 0; hh < 2; hh++) {
                    float v = ss[mt][hh];
                    v += __shfl_xor_sync(0xffffffffu, v, 1);
                    v += __shfl_xor_sync(0xffffffffu, v, 2);
                    if (tig == 0) rsum[(wm * 64 + mt * 16 + g + hh * 8) * 2 + wn] = v;
                }
            __syncthreads();
            float rr[4][2];
            #pragma unroll
            for (int mt = 0; mt < 4; mt++)
                #pragma unroll
                for (int hh = 0; hh < 2; hh++) {
                    int lr = wm * 64 + mt * 16 + g + hh * 8;
                    rr[mt][hh] = rsqrtf((rsum[lr * 2] + rsum[lr * 2 + 1]) * (1.f / HD) + EPSF);
                }
            #pragma unroll
            for (int mt = 0; mt < 4; mt++)
                #pragma unroll
                for (int j = 0; j < 8; j++) {
                    int d = wn * 64 + j * 8 + tig * 2;
                    float b0 = bias[n0 + d], b1 = bias[n0 + d + 1];
                    float s0 = sc[d], s1 = sc[d + 1];
                    #pragma unroll
                    for (int hh = 0; hh < 2; hh++) {
                        int lr = wm * 64 + mt * 16 + g + hh * 8;
                        int l = m0 + lr;
                        float t0 = (acc[mt][j][hh * 2]     + b0) * rr[mt][hh] * s0;
                        float t1 = (acc[mt][j][hh * 2 + 1] + b1) * rr[mt][hh] * s1;
                        float4 p = *(const float4*)(pe + (size_t)l * 256 + d * 2);
                        float o0 = p.x * t0 + p.y * t1;
                        float o1 = p.z * t0 + p.w * t1;
                        *(__half2*)(dbuf + ((size_t)h * LEN + l) * HD + d) =
                            __floats2half2_rn(o0, o1);
                    }
                }
        } else {
            // ---- v tile: bias + fp16, smem transpose -> g_vT ----
            const int h = (n0 - 2 * HID) >> 7;
            __half* vs = (__half*)smem;                      // [128][136]
            #pragma unroll
            for (int mt = 0; mt < 4; mt++)
                #pragma unroll
                for (int j = 0; j < 8; j++) {
                    int d = wn * 64 + j * 8 + tig * 2;
                    float b0 = bias[n0 + d], b1 = bias[n0 + d + 1];
                    #pragma unroll
                    for (int hh = 0; hh < 2; hh++) {
                        int lr = wm * 64 + mt * 16 + g + hh * 8;
                        *(__half2*)(vs + lr * 136 + d) =
                            __floats2half2_rn(acc[mt][j][hh * 2] + b0,
                                              acc[mt][j][hh * 2 + 1] + b1);
                    }
                }
            __syncthreads();
            int d = tid;                                     // 0..127
            __align__(16) __half tmp[128];
            #pragma unroll
            for (int i = 0; i < 128; i++) tmp[i] = vs[i * 136 + d];
            __half* dst = g_vT + ((size_t)h * HD + d) * LEN + m0;
            #pragma unroll
            for (int i = 0; i < 16; i++)
                *(uint4*)(dst + i * 8) = *(uint4*)(tmp + i * 8);
        }
        return;
    }

    #pragma unroll
    for (int mt = 0; mt < 4; mt++) {
        #pragma unroll
        for (int j = 0; j < 8; j++) {
            int row = m0 + wm * 64 + mt * 16 + g;
            int col = n0 + wn * 64 + j * 8 + tig * 2;
            float v00 = acc[mt][j][0], v01 = acc[mt][j][1];
            float v10 = acc[mt][j][2], v11 = acc[mt][j][3];
            if (EPI == 0) {
                float b0 = bias[col], b1 = bias[col + 1];
                float g0 = g_mod[2 * HID + col], g1 = g_mod[2 * HID + col + 1];
                float* C = (float*)Cv;
                float2 x0 = *(const float2*)(xres + (size_t)row * HID + col);
                float2 x1 = *(const float2*)(xres + (size_t)(row + 8) * HID + col);
                float2 a0 = { x0.x + g0 * (v00 + b0), x0.y + g1 * (v01 + b1) };
                float2 a1 = { x1.x + g0 * (v10 + b0), x1.y + g1 * (v11 + b1) };
                *(float2*)(C + (size_t)row * ldC + col) = a0;
                *(float2*)(C + (size_t)(row + 8) * ldC + col) = a1;
            } else {  // EPI == 3, mlp tile
                float b0 = bias[col], b1 = bias[col + 1];
                v00 += b0; v01 += b1; v10 += b0; v11 += b1;
                auto gelu = [](float v) {
                    float inr = 0.7978845608028654f * (v + 0.044715f * v * v * v);
                    return 0.5f * v * (1.f + tanhf(inr));
                };
                int c2 = HID + (col - NQKV);
                *(__half2*)(g_a2 + (size_t)row * N2 + c2) = __floats2half2_rn(gelu(v00), gelu(v01));
                *(__half2*)(g_a2 + (size_t)(row + 8) * N2 + c2) = __floats2half2_rn(gelu(v10), gelu(v11));
            }
        }
    }
}

// ---------------- flash attention (unchanged from R11) -----------------------
#define FA_Q    0
#define FA_KV   40960
#define FA_KVSZ 81920
#define FA_SMEM 204800
#define NKT     (LEN/128)      // 24

__global__ void __launch_bounds__(256, 1) flash_attn() {
    extern __shared__ char smem[];
    const uint32_t sb = smem_u32(smem);
    const int tid = threadIdx.x, lane = tid & 31, wid = tid >> 5;
    const int g = lane >> 2, tig = lane & 3;
    const int m0 = blockIdx.x * 128;
    const int h = blockIdx.y;
    const float alpha = 0.08838834764831845f;

    #pragma unroll
    for (int i = 0; i < 8; i++) {
        int q = tid + (i << 8);
        int r = q >> 4, c = q & 15;
        const __half* src = g_qh + ((size_t)h * LEN + m0 + r) * HD + c * 8;
        uint32_t dst = sb + FA_Q + (c >> 2) * 10240 + r * 80 + (c & 3) * 16;
        asm volatile("cp.async.cg.shared.global [%0], [%1], 16;" :: "r"(dst), "l"(src) : "memory");
    }
    auto load_kv = [&](int j, int buf) {
        #pragma unroll
        for (int i = 0; i < 16; i++) {
            int idx = tid + (i << 8);
            int isV = idx >> 11;
            int e = idx & 2047;
            int r = e >> 4, c = e & 15;
            const __half* src = isV
                ? g_vT + ((size_t)h * HD + r) * LEN + j * 128 + c * 8
                : g_kh + ((size_t)h * LEN + j * 128 + r) * HD + c * 8;
            uint32_t dst = sb + FA_KV + buf * FA_KVSZ + isV * 40960
                         + (c >> 2) * 10240 + r * 80 + (c & 3) * 16;
            asm volatile("cp.async.cg.shared.global [%0], [%1], 16;" :: "r"(dst), "l"(src) : "memory");
        }
    };
    load_kv(0, 0);
    asm volatile("cp.async.commit_group;" ::: "memory");

    float o[16][4];
    #pragma unroll
    for (int a = 0; a < 16; a++)
        #pragma unroll
        for (int b = 0; b < 4; b++) o[a][b] = 0.f;
    float mrow[2] = { -1e30f, -1e30f };
    float lrow[2] = { 0.f, 0.f };

    const int aRow = (lane & 7) + ((lane >> 3) & 1) * 8, aK = (lane >> 4) * 16;
    const int bRow = (lane & 7) + (lane >> 4) * 8,       bK = ((lane >> 3) & 1) * 16;
    const uint32_t qAdr = (uint32_t)((wid * 16 + aRow) * 80 + aK);

    for (int j = 0; j < NKT; j++) {
        __syncthreads();
        if (j + 1 < NKT) load_kv(j + 1, (j + 1) & 1);
        asm volatile("cp.async.commit_group;" ::: "memory");
        asm volatile("cp.async.wait_group 1;" ::: "memory");
        __syncthreads();

        const uint32_t kb = sb + FA_KV + (j & 1) * FA_KVSZ;
        const uint32_t vb = kb + 40960;

        float s[16][4];
        #pragma unroll
        for (int a = 0; a < 16; a++)
            #pragma unroll
            for (int b = 0; b < 4; b++) s[a][b] = 0.f;
        #pragma unroll
        for (int kc = 0; kc < 4; kc++) {
            #pragma unroll
            for (int ks = 0; ks < 2; ks++) {
                uint32_t ra[4], rb[8][4];
                uint32_t ad = sb + FA_Q + kc * 10240 + qAdr + ks * 32;
                asm volatile("ldmatrix.sync.aligned.m8n8.x4.shared.b16 {%0,%1,%2,%3}, [%4];"
                    : "=r"(ra[0]), "=r"(ra[1]), "=r"(ra[2]), "=r"(ra[3]) : "r"(ad));
                #pragma unroll
                for (int bp = 0; bp < 8; bp++) {
                    uint32_t bd = kb + kc * 10240 + (bp * 16 + bRow) * 80 + ks * 32 + bK;
                    asm volatile("ldmatrix.sync.aligned.m8n8.x4.shared.b16 {%0,%1,%2,%3}, [%4];"
                        : "=r"(rb[bp][0]), "=r"(rb[bp][1]), "=r"(rb[bp][2]), "=r"(rb[bp][3])
                        : "r"(bd));
                }
                #pragma unroll
                for (int bp = 0; bp < 8; bp++)
                    #pragma unroll
                    for (int hh = 0; hh < 2; hh++) {
                        float* c = s[bp * 2 + hh];
                        asm volatile(
                            "mma.sync.aligned.m16n8k16.row.col.f32.f16.f16.f32 "
                            "{%0,%1,%2,%3}, {%4,%5,%6,%7}, {%8,%9}, {%0,%1,%2,%3};"
                            : "+f"(c[0]), "+f"(c[1]), "+f"(c[2]), "+f"(c[3])
                            : "r"(ra[0]), "r"(ra[1]), "r"(ra[2]), "r"(ra[3]),
                              "r"(rb[bp][hh * 2]), "r"(rb[bp][hh * 2 + 1]));
                    }
            }
        }

        float mj[2] = { -1e30f, -1e30f };
        #pragma unroll
        for (int nt = 0; nt < 16; nt++) {
            mj[0] = fmaxf(mj[0], fmaxf(s[nt][0], s[nt][1]));
            mj[1] = fmaxf(mj[1], fmaxf(s[nt][2], s[nt][3]));
        }
        #pragma unroll
        for (int hh = 0; hh < 2; hh++) {
            mj[hh] = fmaxf(mj[hh], __shfl_xor_sync(0xffffffffu, mj[hh], 1));
            mj[hh] = fmaxf(mj[hh], __shfl_xor_sync(0xffffffffu, mj[hh], 2));
        }
        float mnew[2] = { fmaxf(mrow[0], mj[0]), fmaxf(mrow[1], mj[1]) };
        float corr[2] = { __expf(alpha * (mrow[0] - mnew[0])),
                          __expf(alpha * (mrow[1] - mnew[1])) };
        mrow[0] = mnew[0]; mrow[1] = mnew[1];

        float rs[2] = { 0.f, 0.f };
        uint32_t phA[16], phB[16];
        #pragma unroll
        for (int nt = 0; nt < 16; nt++) {
            float e0 = __expf(alpha * (s[nt][0] - mnew[0]));
            float e1 = __expf(alpha * (s[nt][1] - mnew[0]));
            float e2 = __expf(alpha * (s[nt][2] - mnew[1]));
            float e3 = __expf(alpha * (s[nt][3] - mnew[1]));
            rs[0] += e0 + e1; rs[1] += e2 + e3;
            __half2 p0 = __floats2half2_rn(e0, e1);
            __half2 p1 = __floats2half2_rn(e2, e3);
            phA[nt] = *(uint32_t*)&p0;
            phB[nt] = *(uint32_t*)&p1;
        }
        #pragma unroll
        for (int hh = 0; hh < 2; hh++) {
            rs[hh] += __shfl_xor_sync(0xffffffffu, rs[hh], 1);
            rs[hh] += __shfl_xor_sync(0xffffffffu, rs[hh], 2);
            lrow[hh] = lrow[hh] * corr[hh] + rs[hh];
        }
        #pragma unroll
        for (int nt = 0; nt < 16; nt++) {
            o[nt][0] *= corr[0]; o[nt][1] *= corr[0];
            o[nt][2] *= corr[1]; o[nt][3] *= corr[1];
        }

        #pragma unroll
        for (int kc = 0; kc < 8; kc++) {
            uint32_t ra[4] = { phA[kc * 2], phB[kc * 2], phA[kc * 2 + 1], phB[kc * 2 + 1] };
            uint32_t rb[8][4];
            #pragma unroll
            for (int bp = 0; bp < 8; bp++) {
                uint32_t bd = vb + (kc >> 1) * 10240 + (bp * 16 + bRow) * 80 + (kc & 1) * 32 + bK;
                asm volatile("ldmatrix.sync.aligned.m8n8.x4.shared.b16 {%0,%1,%2,%3}, [%4];"
                    : "=r"(rb[bp][0]), "=r"(rb[bp][1]), "=r"(rb[bp][2]), "=r"(rb[bp][3])
                    : "r"(bd));
            }
            #pragma unroll
            for (int bp = 0; bp < 8; bp++)
                #pragma unroll
                for (int hh = 0; hh < 2; hh++) {
                    float* c = o[bp * 2 + hh];
                    asm volatile(
                        "mma.sync.aligned.m16n8k16.row.col.f32.f16.f16.f32 "
                        "{%0,%1,%2,%3}, {%4,%5,%6,%7}, {%8,%9}, {%0,%1,%2,%3};"
                        : "+f"(c[0]), "+f"(c[1]), "+f"(c[2]), "+f"(c[3])
                        : "r"(ra[0]), "r"(ra[1]), "r"(ra[2]), "r"(ra[3]),
                          "r"(rb[bp][hh * 2]), "r"(rb[bp][hh * 2 + 1]));
                }
        }
    }

    float inv0 = 1.f / lrow[0], inv1 = 1.f / lrow[1];
    int row0 = m0 + wid * 16 + g;
    #pragma unroll
    for (int nt = 0; nt < 16; nt++) {
        int col = h * 128 + nt * 8 + tig * 2;
        *(__half2*)(g_a2 + (size_t)row0 * N2 + col) =
            __floats2half2_rn(o[nt][0] * inv0, o[nt][1] * inv0);
        *(__half2*)(g_a2 + (size_t)(row0 + 8) * N2 + col) =
            __floats2half2_rn(o[nt][2] * inv1, o[nt][3] * inv1);
    }
}

// ---------------- elementwise ------------------------------------------------
__global__ void gemv_mod_kernel(const float* __restrict__ vec,
                                const float* __restrict__ W, const float* __restrict__ b) {
    int j = blockIdx.x * 8 + (threadIdx.x >> 5);
    int lane = threadIdx.x & 31;
    const float4* w4 = (const float4*)(W + (size_t)j * HID);
    const float4* v4 = (const float4*)vec;
    float acc = 0.f;
    for (int i = lane; i < HID/4; i += 32) {
        float4 w = w4[i], v = v4[i];
        acc += w.x * (v.x / (1.f + __expf(-v.x)));
        acc += w.y * (v.y / (1.f + __expf(-v.y)));
        acc += w.z * (v.z / (1.f + __expf(-v.z)));
        acc += w.w * (v.w / (1.f + __expf(-v.w)));
    }
    #pragma unroll
    for (int o = 16; o; o >>= 1) acc += __shfl_xor_sync(0xffffffffu, acc, o);
    if (lane == 0) g_mod[j] = acc + b[j];
}

__global__ void layernorm_kernel(const float* __restrict__ x) {
    __shared__ float shA[8], shB[8];
    __shared__ float s_mu, s_r;
    int l = blockIdx.x, t = threadIdx.x;
    const float* row = x + (size_t)l * HID;
    float v[12];
    float s = 0.f, ss = 0.f;
    #pragma unroll
    for (int i = 0; i < 12; i++) { v[i] = row[t + i*256]; s += v[i]; ss += v[i]*v[i]; }
    #pragma unroll
    for (int o = 16; o; o >>= 1) {
        s  += __shfl_xor_sync(0xffffffffu, s, o);
        ss += __shfl_xor_sync(0xffffffffu, ss, o);
    }
    if ((t & 31) == 0) { shA[t>>5] = s; shB[t>>5] = ss; }
    __syncthreads();
    if (t == 0) {
        float a = 0.f, bb = 0.f;
        #pragma unroll
        for (int w = 0; w < 8; w++) { a += shA[w]; bb += shB[w]; }
        float mu = a / HID;
        s_mu = mu; s_r = rsqrtf(bb / HID - mu*mu + EPSF);
    }
    __syncthreads();
    float mu = s_mu, r = s_r;
    __half* orow = g_a1 + (size_t)l * HID;
    #pragma unroll
    for (int i = 0; i < 12; i++) {
        int kc = t + i*256;
        float xm = (v[i] - mu) * r * (1.f + g_mod[HID + kc]) + g_mod[kc];
        orow[kc] = __float2half_rn(xm);
    }
}

// fp32 -> fp16 grid-stride (R11-proven version)
__global__ void conv_w(const float4* __restrict__ src, uint2* __restrict__ dst, size_t n4) {
    size_t stride = (size_t)gridDim.x * blockDim.x;
    for (size_t i = (size_t)blockIdx.x * blockDim.x + threadIdx.x; i < n4; i += stride) {
        float4 v = src[i];
        __half2 h0 = __floats2half2_rn(v.x, v.y);
        __half2 h1 = __floats2half2_rn(v.z, v.w);
        uint2 u = { *(uint32_t*)&h0, *(uint32_t*)&h1 };
        dst[i] = u;
    }
}

// ---------------- launcher ---------------------------------------------------
extern "C" void kernel_launch(void* const* d_in, const int* in_sizes, int n_in,
                              void* d_out, int out_size) {
    const float* x       = (const float*)d_in[0];
    const float* vec     = (const float*)d_in[1];
    const float* pe      = (const float*)d_in[2];
    const float* mod_w   = (const float*)d_in[3];
    const float* mod_b   = (const float*)d_in[4];
    const float* lin1_w  = (const float*)d_in[5];
    const float* lin1_b  = (const float*)d_in[6];
    const float* lin2_w  = (const float*)d_in[7];
    const float* lin2_b  = (const float*)d_in[8];
    const float* q_scale = (const float*)d_in[9];
    const float* k_scale = (const float*)d_in[10];
    float* out = (float*)d_out;

    void *pa1, *pw1, *pa2, *pw2;
    cudaGetSymbolAddress(&pa1, g_a1);   cudaGetSymbolAddress(&pw1, g_w1);
    cudaGetSymbolAddress(&pa2, g_a2);   cudaGetSymbolAddress(&pw2, g_w2);

    cudaFuncSetAttribute(gemm_h<0>, cudaFuncAttributeMaxDynamicSharedMemorySize, SMEMB);
    cudaFuncSetAttribute(gemm_h<3>, cudaFuncAttributeMaxDynamicSharedMemorySize, SMEMB);
    cudaFuncSetAttribute(flash_attn, cudaFuncAttributeMaxDynamicSharedMemorySize, FA_SMEM);

    gemv_mod_kernel<<<(3*HID)/8, 256>>>(vec, mod_w, mod_b);                 // 1
    layernorm_kernel<<<LEN, 256>>>(x);                                      // 2
    conv_w<<<2048, 256>>>((const float4*)lin1_w, (uint2*)pw1, (size_t)N1*HID/4); // 3

    // 4 (profiled): lin1 M=3072 N=21504 K=3072; epilogue does RMS/RoPE/vT/gelu
    gemm_h<3><<<dim3(LEN/128, N1/128, 1), 128, SMEMB>>>(
        (const __half*)pa1, (const __half*)pw1, lin1_b, nullptr,
        0, HID, pe, q_scale, k_scale, nullptr);

    conv_w<<<2048, 256>>>((const float4*)lin2_w, (uint2*)pw2, (size_t)HID*N2/4); // 5

    // 6: fused attention -> g_a2[:, h*128+d]
    flash_attn<<<dim3(LEN/128, NH), 256, FA_SMEM>>>();

    // 7: lin2 M=3072 N=3072 K=15360 -> out = x + gate*(acc+bias)
    gemm_h<0><<<dim3(LEN/128, HID/128, 1), 128, SMEMB>>>(
        (const __half*)pa2, (const __half*)pw2, lin2_b, out,
        HID, N2, nullptr, nullptr, nullptr, x);
}

// round 15
// speedup vs baseline: 1.0228x; 1.0096x over previous
#include <cuda_runtime.h>
#include <cuda_fp16.h>
#include <math.h>
#include <stdint.h>

#define LEN   3072
#define HID   3072
#define NH    24
#define HD    128
#define MLPD  12288
#define N1    (3*HID + MLPD)   // 21504
#define N2    (HID + MLPD)     // 15360
#define NQKV  (3*HID)          // 9216
#define EPSF  1e-6f

// ---------------- scratch ----------------------------------------------------
__device__ float g_mod[3*HID];
__device__ __align__(256) __half g_a1[(size_t)LEN*HID];
__device__ __align__(256) __half g_w1[(size_t)N1*HID];
__device__ __align__(256) __half g_a2[(size_t)LEN*N2];          // [attn | gelu(mlp)]
__device__ __align__(256) __half g_w2[(size_t)HID*N2];
__device__ __align__(256) __half g_qh[(size_t)NH*LEN*HD];
__device__ __align__(256) __half g_kh[(size_t)NH*LEN*HD];
__device__ __align__(256) __half g_vT[(size_t)NH*HD*LEN];       // [h][d][l]

__device__ __forceinline__ uint32_t smem_u32(const void* p) {
    uint32_t a;
    asm("{ .reg .u64 t; cvta.to.shared.u64 t, %1; cvt.u32.u64 %0, t; }" : "=r"(a) : "l"(p));
    return a;
}

// ------- fp16 HMMA GEMM: 128x128 tile, 4 warps (2x2) of 64x64, 2 CTA/SM -----
#define PITCH 80
#define ATILE (128*PITCH)
#define STGSZ (2*ATILE)
#define NSTG  3
#define SMEMB (NSTG*STGSZ)            // 61440

// EPI: 0 = lin2: fp32 out = xres + gate*(acc+bias)
//      3 = lin1: q/k tiles -> RMS+RoPE -> g_qh/g_kh; v tiles -> transpose -> g_vT;
//          mlp tiles -> gelu -> g_a2
template<int EPI>
__global__ void __launch_bounds__(128, 2) gemm_h(
    const __half* __restrict__ A, const __half* __restrict__ B,
    const float* __restrict__ bias, void* __restrict__ Cv,
    int ldC, int K,
    const float* __restrict__ pe, const float* __restrict__ qsc,
    const float* __restrict__ ksc, const float* __restrict__ xres)
{
    extern __shared__ char smem[];
    const uint32_t sb = smem_u32(smem);
    const int tid = threadIdx.x, lane = tid & 31, wid = tid >> 5;
    const int wm = wid & 1, wn = wid >> 1;            // 2m x 2n warps, 64x64 each
    const int m0 = blockIdx.x * 128, n0 = blockIdx.y * 128;
    const int KT = K >> 5;

    auto load_stage = [&](int buf, int kt) {
        const int k0 = kt << 5;
        #pragma unroll
        for (int i = 0; i < 8; i++) {                 // 1024 chunks / 128 thr
            int idx = tid + (i << 7);
            int isB = idx >> 9;
            int r = (idx & 511) >> 2, ch = idx & 3;
            const __half* src = (isB ? B + (size_t)(n0 + r) * K
                                     : A + (size_t)(m0 + r) * K) + k0 + ch * 8;
            uint32_t dst = sb + buf * STGSZ + isB * ATILE + r * PITCH + ch * 16;
            asm volatile("cp.async.cg.shared.global [%0], [%1], 16;"
                         :: "r"(dst), "l"(src) : "memory");
        }
    };

    float acc[4][8][4];
    #pragma unroll
    for (int a = 0; a < 4; a++)
        #pragma unroll
        for (int b = 0; b < 8; b++)
            #pragma unroll
            for (int c = 0; c < 4; c++) acc[a][b][c] = 0.f;

    const int aRow = (lane & 7) + ((lane >> 3) & 1) * 8, aK = (lane >> 4) * 16;
    const int bRow = (lane & 7) + (lane >> 4) * 8,       bK = ((lane >> 3) & 1) * 16;
    const uint32_t aAdr0 = (uint32_t)((wm * 64 + aRow) * PITCH + aK);
    const uint32_t bAdr0 = (uint32_t)(ATILE + (wn * 64 + bRow) * PITCH + bK);

    load_stage(0, 0);
    asm volatile("cp.async.commit_group;" ::: "memory");
    if (KT > 1) load_stage(1, 1);
    asm volatile("cp.async.commit_group;" ::: "memory");

    for (int kt = 0; kt < KT; kt++) {
        asm volatile("cp.async.wait_group 1;" ::: "memory");
        __syncthreads();
        int nk = kt + 2;
        if (nk < KT) load_stage(nk % NSTG, nk);
        asm volatile("cp.async.commit_group;" ::: "memory");

        const uint32_t base = sb + (kt % NSTG) * STGSZ;
        #pragma unroll
        for (int ks = 0; ks < 2; ks++) {
            uint32_t ra[4][4], rb[4][4];
            #pragma unroll
            for (int mt = 0; mt < 4; mt++) {
                uint32_t ad = base + aAdr0 + mt * (16 * PITCH) + ks * 32;
                asm volatile("ldmatrix.sync.aligned.m8n8.x4.shared.b16 {%0,%1,%2,%3}, [%4];"
                    : "=r"(ra[mt][0]), "=r"(ra[mt][1]), "=r"(ra[mt][2]), "=r"(ra[mt][3])
                    : "r"(ad));
            }
            #pragma unroll
            for (int nt = 0; nt < 4; nt++) {
                uint32_t bd = base + bAdr0 + nt * (16 * PITCH) + ks * 32;
                asm volatile("ldmatrix.sync.aligned.m8n8.x4.shared.b16 {%0,%1,%2,%3}, [%4];"
                    : "=r"(rb[nt][0]), "=r"(rb[nt][1]), "=r"(rb[nt][2]), "=r"(rb[nt][3])
                    : "r"(bd));
            }
            #pragma unroll
            for (int mt = 0; mt < 4; mt++)
                #pragma unroll
                for (int nt = 0; nt < 4; nt++) {
                    #pragma unroll
                    for (int h = 0; h < 2; h++) {
                        float* c = acc[mt][nt * 2 + h];
                        asm volatile(
                            "mma.sync.aligned.m16n8k16.row.col.f32.f16.f16.f32 "
                            "{%0,%1,%2,%3}, {%4,%5,%6,%7}, {%8,%9}, {%0,%1,%2,%3};"
                            : "+f"(c[0]), "+f"(c[1]), "+f"(c[2]), "+f"(c[3])
                            : "r"(ra[mt][0]), "r"(ra[mt][1]), "r"(ra[mt][2]), "r"(ra[mt][3]),
                              "r"(rb[nt][h * 2]), "r"(rb[nt][h * 2 + 1]));
                    }
                }
        }
        __syncthreads();
    }

    const int g = lane >> 2, tig = lane & 3;

    if (EPI == 3 && n0 < NQKV) {
        asm volatile("cp.async.wait_group 0;" ::: "memory");
        __syncthreads();
        if (n0 < 2 * HID) {
            // ---- q or k tile: bias + RMS + RoPE + fp16 store ----
            const bool isq = (n0 < HID);
            const int h = (n0 - (isq ? 0 : HID)) >> 7;
            const float* sc = isq ? qsc : ksc;
            __half* dbuf = isq ? g_qh : g_kh;
            float* rsum = (float*)smem;                      // [128][2]
            float ss[4][2];
            #pragma unroll
            for (int mt = 0; mt < 4; mt++) { ss[mt][0] = 0.f; ss[mt][1] = 0.f; }
            #pragma unroll
            for (int mt = 0; mt < 4; mt++)
                #pragma unroll
                for (int j = 0; j < 8; j++) {
                    int col = wn * 64 + j * 8 + tig * 2;
                    float b0 = bias[n0 + col], b1 = bias[n0 + col + 1];
                    float t00 = acc[mt][j][0] + b0, t01 = acc[mt][j][1] + b1;
                    float t10 = acc[mt][j][2] + b0, t11 = acc[mt][j][3] + b1;
                    ss[mt][0] += t00 * t00 + t01 * t01;
                    ss[mt][1] += t10 * t10 + t11 * t11;
                }
            #pragma unroll
            for (int mt = 0; mt < 4; mt++)
                #pragma unroll
                for (int hh = 0; hh < 2; hh++) {
                    float v = ss[mt][hh];
                    v += __shfl_xor_sync(0xffffffffu, v, 1);
                    v += __shfl_xor_sync(0xffffffffu, v, 2);
                    if (tig == 0) rsum[(wm * 64 + mt * 16 + g + hh * 8) * 2 + wn] = v;
                }
            __syncthreads();
            float rr[4][2];
            #pragma unroll
            for (int mt = 0; mt < 4; mt++)
                #pragma unroll
                for (int hh = 0; hh < 2; hh++) {
                    int lr = wm * 64 + mt * 16 + g + hh * 8;
                    rr[mt][hh] = rsqrtf((rsum[lr * 2] + rsum[lr * 2 + 1]) * (1.f / HD) + EPSF);
                }
            #pragma unroll
            for (int mt = 0; mt < 4; mt++)
                #pragma unroll
                for (int j = 0; j < 8; j++) {
                    int d = wn * 64 + j * 8 + tig * 2;
                    float b0 = bias[n0 + d], b1 = bias[n0 + d + 1];
                    float s0 = sc[d], s1 = sc[d + 1];
                    #pragma unroll
                    for (int hh = 0; hh < 2; hh++) {
                        int lr = wm * 64 + mt * 16 + g + hh * 8;
                        int l = m0 + lr;
                        float t0 = (acc[mt][j][hh * 2]     + b0) * rr[mt][hh] * s0;
                        float t1 = (acc[mt][j][hh * 2 + 1] + b1) * rr[mt][hh] * s1;
                        float4 p = *(const float4*)(pe + (size_t)l * 256 + d * 2);
                        float o0 = p.x * t0 + p.y * t1;
                        float o1 = p.z * t0 + p.w * t1;
                        *(__half2*)(dbuf + ((size_t)h * LEN + l) * HD + d) =
                            __floats2half2_rn(o0, o1);
                    }
                }
        } else {
            // ---- v tile: bias + fp16, smem transpose -> g_vT ----
            const int h = (n0 - 2 * HID) >> 7;
            __half* vs = (__half*)smem;                      // [128][136]
            #pragma unroll
            for (int mt = 0; mt < 4; mt++)
                #pragma unroll
                for (int j = 0; j < 8; j++) {
                    int d = wn * 64 + j * 8 + tig * 2;
                    float b0 = bias[n0 + d], b1 = bias[n0 + d + 1];
                    #pragma unroll
                    for (int hh = 0; hh < 2; hh++) {
                        int lr = wm * 64 + mt * 16 + g + hh * 8;
                        *(__half2*)(vs + lr * 136 + d) =
                            __floats2half2_rn(acc[mt][j][hh * 2] + b0,
                                              acc[mt][j][hh * 2 + 1] + b1);
                    }
                }
            __syncthreads();
            int d = tid;                                     // 0..127
            __align__(16) __half tmp[128];
            #pragma unroll
            for (int i = 0; i < 128; i++) tmp[i] = vs[i * 136 + d];
            __half* dst = g_vT + ((size_t)h * HD + d) * LEN + m0;
            #pragma unroll
            for (int i = 0; i < 16; i++)
                *(uint4*)(dst + i * 8) = *(uint4*)(tmp + i * 8);
        }
        return;
    }

    #pragma unroll
    for (int mt = 0; mt < 4; mt++) {
        #pragma unroll
        for (int j = 0; j < 8; j++) {
            int row = m0 + wm * 64 + mt * 16 + g;
            int col = n0 + wn * 64 + j * 8 + tig * 2;
            float v00 = acc[mt][j][0], v01 = acc[mt][j][1];
            float v10 = acc[mt][j][2], v11 = acc[mt][j][3];
            if (EPI == 0) {
                float b0 = bias[col], b1 = bias[col + 1];
                float g0 = g_mod[2 * HID + col], g1 = g_mod[2 * HID + col + 1];
                float* C = (float*)Cv;
                float2 x0 = *(const float2*)(xres + (size_t)row * HID + col);
                float2 x1 = *(const float2*)(xres + (size_t)(row + 8) * HID + col);
                float2 a0 = { x0.x + g0 * (v00 + b0), x0.y + g1 * (v01 + b1) };
                float2 a1 = { x1.x + g0 * (v10 + b0), x1.y + g1 * (v11 + b1) };
                *(float2*)(C + (size_t)row * ldC + col) = a0;
                *(float2*)(C + (size_t)(row + 8) * ldC + col) = a1;
            } else {  // EPI == 3, mlp tile
                float b0 = bias[col], b1 = bias[col + 1];
                v00 += b0; v01 += b1; v10 += b0; v11 += b1;
                auto gelu = [](float v) {
                    float inr = 0.7978845608028654f * (v + 0.044715f * v * v * v);
                    return 0.5f * v * (1.f + tanhf(inr));
                };
                int c2 = HID + (col - NQKV);
                *(__half2*)(g_a2 + (size_t)row * N2 + c2) = __floats2half2_rn(gelu(v00), gelu(v01));
                *(__half2*)(g_a2 + (size_t)(row + 8) * N2 + c2) = __floats2half2_rn(gelu(v10), gelu(v11));
            }
        }
    }
}

// ---------------- flash attention --------------------------------------------
#define FA_Q    0
#define FA_KV   40960
#define FA_KVSZ 81920
#define FA_SMEM 204800
#define NKT     (LEN/128)      // 24

__global__ void __launch_bounds__(256, 1) flash_attn() {
    extern __shared__ char smem[];
    const uint32_t sb = smem_u32(smem);
    const int tid = threadIdx.x, lane = tid & 31, wid = tid >> 5;
    const int g = lane >> 2, tig = lane & 3;
    const int m0 = blockIdx.x * 128;
    const int h = blockIdx.y;
    const float alpha = 0.08838834764831845f;

    #pragma unroll
    for (int i = 0; i < 8; i++) {
        int q = tid + (i << 8);
        int r = q >> 4, c = q & 15;
        const __half* src = g_qh + ((size_t)h * LEN + m0 + r) * HD + c * 8;
        uint32_t dst = sb + FA_Q + (c >> 2) * 10240 + r * 80 + (c & 3) * 16;
        asm volatile("cp.async.cg.shared.global [%0], [%1], 16;" :: "r"(dst), "l"(src) : "memory");
    }
    auto load_kv = [&](int j, int buf) {
        #pragma unroll
        for (int i = 0; i < 16; i++) {
            int idx = tid + (i << 8);
            int isV = idx >> 11;
            int e = idx & 2047;
            int r = e >> 4, c = e & 15;
            const __half* src = isV
                ? g_vT + ((size_t)h * HD + r) * LEN + j * 128 + c * 8
                : g_kh + ((size_t)h * LEN + j * 128 + r) * HD + c * 8;
            uint32_t dst = sb + FA_KV + buf * FA_KVSZ + isV * 40960
                         + (c >> 2) * 10240 + r * 80 + (c & 3) * 16;
            asm volatile("cp.async.cg.shared.global [%0], [%1], 16;" :: "r"(dst), "l"(src) : "memory");
        }
    };
    load_kv(0, 0);
    asm volatile("cp.async.commit_group;" ::: "memory");

    float o[16][4];
    #pragma unroll
    for (int a = 0; a < 16; a++)
        #pragma unroll
        for (int b = 0; b < 4; b++) o[a][b] = 0.f;
    float mrow[2] = { -1e30f, -1e30f };
    float lrow[2] = { 0.f, 0.f };

    const int aRow = (lane & 7) + ((lane >> 3) & 1) * 8, aK = (lane >> 4) * 16;
    const int bRow = (lane & 7) + (lane >> 4) * 8,       bK = ((lane >> 3) & 1) * 16;
    const uint32_t qAdr = (uint32_t)((wid * 16 + aRow) * 80 + aK);

    for (int j = 0; j < NKT; j++) {
        __syncthreads();
        if (j + 1 < NKT) load_kv(j + 1, (j + 1) & 1);
        asm volatile("cp.async.commit_group;" ::: "memory");
        asm volatile("cp.async.wait_group 1;" ::: "memory");
        __syncthreads();

        const uint32_t kb = sb + FA_KV + (j & 1) * FA_KVSZ;
        const uint32_t vb = kb + 40960;

        float s[16][4];
        #pragma unroll
        for (int a = 0; a < 16; a++)
            #pragma unroll
            for (int b = 0; b < 4; b++) s[a][b] = 0.f;
        #pragma unroll
        for (int kc = 0; kc < 4; kc++) {
            #pragma unroll
            for (int ks = 0; ks < 2; ks++) {
                uint32_t ra[4], rb[8][4];
                uint32_t ad = sb + FA_Q + kc * 10240 + qAdr + ks * 32;
                asm volatile("ldmatrix.sync.aligned.m8n8.x4.shared.b16 {%0,%1,%2,%3}, [%4];"
                    : "=r"(ra[0]), "=r"(ra[1]), "=r"(ra[2]), "=r"(ra[3]) : "r"(ad));
                #pragma unroll
                for (int bp = 0; bp < 8; bp++) {
                    uint32_t bd = kb + kc * 10240 + (bp * 16 + bRow) * 80 + ks * 32 + bK;
                    asm volatile("ldmatrix.sync.aligned.m8n8.x4.shared.b16 {%0,%1,%2,%3}, [%4];"
                        : "=r"(rb[bp][0]), "=r"(rb[bp][1]), "=r"(rb[bp][2]), "=r"(rb[bp][3])
                        : "r"(bd));
                }
                #pragma unroll
                for (int bp = 0; bp < 8; bp++)
                    #pragma unroll
                    for (int hh = 0; hh < 2; hh++) {
                        float* c = s[bp * 2 + hh];
                        asm volatile(
                            "mma.sync.aligned.m16n8k16.row.col.f32.f16.f16.f32 "
                            "{%0,%1,%2,%3}, {%4,%5,%6,%7}, {%8,%9}, {%0,%1,%2,%3};"
                            : "+f"(c[0]), "+f"(c[1]), "+f"(c[2]), "+f"(c[3])
                            : "r"(ra[0]), "r"(ra[1]), "r"(ra[2]), "r"(ra[3]),
                              "r"(rb[bp][hh * 2]), "r"(rb[bp][hh * 2 + 1]));
                    }
            }
        }

        float mj[2] = { -1e30f, -1e30f };
        #pragma unroll
        for (int nt = 0; nt < 16; nt++) {
            mj[0] = fmaxf(mj[0], fmaxf(s[nt][0], s[nt][1]));
            mj[1] = fmaxf(mj[1], fmaxf(s[nt][2], s[nt][3]));
        }
        #pragma unroll
        for (int hh = 0; hh < 2; hh++) {
            mj[hh] = fmaxf(mj[hh], __shfl_xor_sync(0xffffffffu, mj[hh], 1));
            mj[hh] = fmaxf(mj[hh], __shfl_xor_sync(0xffffffffu, mj[hh], 2));
        }
        float mnew[2] = { fmaxf(mrow[0], mj[0]), fmaxf(mrow[1], mj[1]) };
        float corr[2] = { __expf(alpha * (mrow[0] - mnew[0])),
                          __expf(alpha * (mrow[1] - mnew[1])) };
        mrow[0] = mnew[0]; mrow[1] = mnew[1];

        float rs[2] = { 0.f, 0.f };
        uint32_t phA[16], phB[16];
        #pragma unroll
        for (int nt = 0; nt < 16; nt++) {
            float e0 = __expf(alpha * (s[nt][0] - mnew[0]));
            float e1 = __expf(alpha * (s[nt][1] - mnew[0]));
            float e2 = __expf(alpha * (s[nt][2] - mnew[1]));
            float e3 = __expf(alpha * (s[nt][3] - mnew[1]));
            rs[0] += e0 + e1; rs[1] += e2 + e3;
            __half2 p0 = __floats2half2_rn(e0, e1);
            __half2 p1 = __floats2half2_rn(e2, e3);
            phA[nt] = *(uint32_t*)&p0;
            phB[nt] = *(uint32_t*)&p1;
        }
        #pragma unroll
        for (int hh = 0; hh < 2; hh++) {
            rs[hh] += __shfl_xor_sync(0xffffffffu, rs[hh], 1);
            rs[hh] += __shfl_xor_sync(0xffffffffu, rs[hh], 2);
            lrow[hh] = lrow[hh] * corr[hh] + rs[hh];
        }
        #pragma unroll
        for (int nt = 0; nt < 16; nt++) {
            o[nt][0] *= corr[0]; o[nt][1] *= corr[0];
            o[nt][2] *= corr[1]; o[nt][3] *= corr[1];
        }

        #pragma unroll
        for (int kc = 0; kc < 8; kc++) {
            uint32_t ra[4] = { phA[kc * 2], phB[kc * 2], phA[kc * 2 + 1], phB[kc * 2 + 1] };
            uint32_t rb[8][4];
            #pragma unroll
            for (int bp = 0; bp < 8; bp++) {
                uint32_t bd = vb + (kc >> 1) * 10240 + (bp * 16 + bRow) * 80 + (kc & 1) * 32 + bK;
                asm volatile("ldmatrix.sync.aligned.m8n8.x4.shared.b16 {%0,%1,%2,%3}, [%4];"
                    : "=r"(rb[bp][0]), "=r"(rb[bp][1]), "=r"(rb[bp][2]), "=r"(rb[bp][3])
                    : "r"(bd));
            }
            #pragma unroll
            for (int bp = 0; bp < 8; bp++)
                #pragma unroll
                for (int hh = 0; hh < 2; hh++) {
                    float* c = o[bp * 2 + hh];
                    asm volatile(
                        "mma.sync.aligned.m16n8k16.row.col.f32.f16.f16.f32 "
                        "{%0,%1,%2,%3}, {%4,%5,%6,%7}, {%8,%9}, {%0,%1,%2,%3};"
                        : "+f"(c[0]), "+f"(c[1]), "+f"(c[2]), "+f"(c[3])
                        : "r"(ra[0]), "r"(ra[1]), "r"(ra[2]), "r"(ra[3]),
                          "r"(rb[bp][hh * 2]), "r"(rb[bp][hh * 2 + 1]));
                }
        }
    }

    float inv0 = 1.f / lrow[0], inv1 = 1.f / lrow[1];
    int row0 = m0 + wid * 16 + g;
    #pragma unroll
    for (int nt = 0; nt < 16; nt++) {
        int col = h * 128 + nt * 8 + tig * 2;
        *(__half2*)(g_a2 + (size_t)row0 * N2 + col) =
            __floats2half2_rn(o[nt][0] * inv0, o[nt][1] * inv0);
        *(__half2*)(g_a2 + (size_t)(row0 + 8) * N2 + col) =
            __floats2half2_rn(o[nt][2] * inv1, o[nt][3] * inv1);
    }
}

// ---------------- elementwise ------------------------------------------------
__global__ void gemv_mod_kernel(const float* __restrict__ vec,
                                const float* __restrict__ W, const float* __restrict__ b) {
    int j = blockIdx.x * 8 + (threadIdx.x >> 5);
    int lane = threadIdx.x & 31;
    const float4* w4 = (const float4*)(W + (size_t)j * HID);
    const float4* v4 = (const float4*)vec;
    float acc = 0.f;
    for (int i = lane; i < HID/4; i += 32) {
        float4 w = w4[i], v = v4[i];
        acc += w.x * (v.x / (1.f + __expf(-v.x)));
        acc += w.y * (v.y / (1.f + __expf(-v.y)));
        acc += w.z * (v.z / (1.f + __expf(-v.z)));
        acc += w.w * (v.w / (1.f + __expf(-v.w)));
    }
    #pragma unroll
    for (int o = 16; o; o >>= 1) acc += __shfl_xor_sync(0xffffffffu, acc, o);
    if (lane == 0) g_mod[j] = acc + b[j];
}

__global__ void layernorm_kernel(const float* __restrict__ x) {
    __shared__ float shA[8], shB[8];
    __shared__ float s_mu, s_r;
    int l = blockIdx.x, t = threadIdx.x;
    const float* row = x + (size_t)l * HID;
    float v[12];
    float s = 0.f, ss = 0.f;
    #pragma unroll
    for (int i = 0; i < 12; i++) { v[i] = row[t + i*256]; s += v[i]; ss += v[i]*v[i]; }
    #pragma unroll
    for (int o = 16; o; o >>= 1) {
        s  += __shfl_xor_sync(0xffffffffu, s, o);
        ss += __shfl_xor_sync(0xffffffffu, ss, o);
    }
    if ((t & 31) == 0) { shA[t>>5] = s; shB[t>>5] = ss; }
    __syncthreads();
    if (t == 0) {
        float a = 0.f, bb = 0.f;
        #pragma unroll
        for (int w = 0; w < 8; w++) { a += shA[w]; bb += shB[w]; }
        float mu = a / HID;
        s_mu = mu; s_r = rsqrtf(bb / HID - mu*mu + EPSF);
    }
    __syncthreads();
    float mu = s_mu, r = s_r;
    __half* orow = g_a1 + (size_t)l * HID;
    #pragma unroll
    for (int i = 0; i < 12; i++) {
        int kc = t + i*256;
        float xm = (v[i] - mu) * r * (1.f + g_mod[HID + kc]) + g_mod[kc];
        orow[kc] = __float2half_rn(xm);
    }
}

// fp32 -> fp16 grid-stride
__global__ void conv_w(const float4* __restrict__ src, uint2* __restrict__ dst, size_t n4) {
    size_t stride = (size_t)gridDim.x * blockDim.x;
    for (size_t i = (size_t)blockIdx.x * blockDim.x + threadIdx.x; i < n4; i += stride) {
        float4 v = src[i];
        __half2 h0 = __floats2half2_rn(v.x, v.y);
        __half2 h1 = __floats2half2_rn(v.z, v.w);
        uint2 u = { *(uint32_t*)&h0, *(uint32_t*)&h1 };
        dst[i] = u;
    }
}

// ---------------- launcher ---------------------------------------------------
extern "C" void kernel_launch(void* const* d_in, const int* in_sizes, int n_in,
                              void* d_out, int out_size) {
    const float* x       = (const float*)d_in[0];
    const float* vec     = (const float*)d_in[1];
    const float* pe      = (const float*)d_in[2];
    const float* mod_w   = (const float*)d_in[3];
    const float* mod_b   = (const float*)d_in[4];
    const float* lin1_w  = (const float*)d_in[5];
    const float* lin1_b  = (const float*)d_in[6];
    const float* lin2_w  = (const float*)d_in[7];
    const float* lin2_b  = (const float*)d_in[8];
    const float* q_scale = (const float*)d_in[9];
    const float* k_scale = (const float*)d_in[10];
    float* out = (float*)d_out;

    void *pa1, *pw1, *pa2, *pw2;
    cudaGetSymbolAddress(&pa1, g_a1);   cudaGetSymbolAddress(&pw1, g_w1);
    cudaGetSymbolAddress(&pa2, g_a2);   cudaGetSymbolAddress(&pw2, g_w2);

    cudaFuncSetAttribute(gemm_h<0>, cudaFuncAttributeMaxDynamicSharedMemorySize, SMEMB);
    cudaFuncSetAttribute(gemm_h<3>, cudaFuncAttributeMaxDynamicSharedMemorySize, SMEMB);
    cudaFuncSetAttribute(flash_attn, cudaFuncAttributeMaxDynamicSharedMemorySize, FA_SMEM);

    // one-time host-side setup (created on the uncaptured correctness call,
    // reused during graph capture; no device work depends on call count)
    static cudaStream_t s_w1 = nullptr, s_w2 = nullptr;
    static cudaEvent_t evRoot = nullptr, evW1 = nullptr, evW2 = nullptr;
    if (s_w1 == nullptr) {
        cudaStreamCreateWithFlags(&s_w1, cudaStreamNonBlocking);
        cudaStreamCreateWithFlags(&s_w2, cudaStreamNonBlocking);
        cudaEventCreateWithFlags(&evRoot, cudaEventDisableTiming);
        cudaEventCreateWithFlags(&evW1,   cudaEventDisableTiming);
        cudaEventCreateWithFlags(&evW2,   cudaEventDisableTiming);
    }

    // fork both weight conversions off the main stream
    cudaEventRecord(evRoot, 0);
    cudaStreamWaitEvent(s_w1, evRoot, 0);
    cudaStreamWaitEvent(s_w2, evRoot, 0);
    conv_w<<<2048, 256, 0, s_w1>>>((const float4*)lin1_w, (uint2*)pw1, (size_t)N1*HID/4);
    cudaEventRecord(evW1, s_w1);
    conv_w<<<2048, 256, 0, s_w2>>>((const float4*)lin2_w, (uint2*)pw2, (size_t)HID*N2/4);
    cudaEventRecord(evW2, s_w2);

    // main stream: mod GEMV + LN (overlapped with conv_w1/conv_w2)
    gemv_mod_kernel<<<(3*HID)/8, 256>>>(vec, mod_w, mod_b);
    layernorm_kernel<<<LEN, 256>>>(x);

    // lin1 needs w1
    cudaStreamWaitEvent(0, evW1, 0);
    gemm_h<3><<<dim3(LEN/128, N1/128, 1), 128, SMEMB>>>(
        (const __half*)pa1, (const __half*)pw1, lin1_b, nullptr,
        0, HID, pe, q_scale, k_scale, nullptr);

    // fused attention (conv_w2 still overlapping underneath)
    flash_attn<<<dim3(LEN/128, NH), 256, FA_SMEM>>>();

    // lin2 needs w2
    cudaStreamWaitEvent(0, evW2, 0);
    gemm_h<0><<<dim3(LEN/128, HID/128, 1), 128, SMEMB>>>(
        (const __half*)pa2, (const __half*)pw2, lin2_b, out,
        HID, N2, nullptr, nullptr, nullptr, x);
}